// round 7
// baseline (speedup 1.0000x reference)
#include <cuda_runtime.h>
#include <cuda_bf16.h>
#include <cfloat>

#define LEVELS 255.0f
#define EPS 1e-8f

// One CTA per row. Row = 16384 fp32 = 4096 float4; 1024 threads x 4 float4.
// v7: REDUX.SYNC-based min/max reduction (monotonic float<->u32 key) to cut
// ~300 cycles of SHFL dependency chain out of each CTA's memory-idle window.
// Otherwise identical to the best kernel (R5): .cs hints, one barrier,
// centered-clamp epilogue.

// monotonic order-preserving float->u32 key (no NaNs in input)
__device__ __forceinline__ unsigned f2key(float f) {
    unsigned u = __float_as_uint(f);
    return (u & 0x80000000u) ? ~u : (u | 0x80000000u);
}
__device__ __forceinline__ float key2f(unsigned k) {
    unsigned u = (k & 0x80000000u) ? (k & 0x7FFFFFFFu) : ~k;
    return __uint_as_float(u);
}

__global__ __launch_bounds__(1024, 2)
void perchannel_quant_kernel(const float* __restrict__ x,
                             float* __restrict__ out)
{
    const int row = blockIdx.x;
    const int tid = threadIdx.x;

    const float4* __restrict__ xrow =
        reinterpret_cast<const float4*>(x) + (size_t)row * 4096;
    float4* __restrict__ orow =
        reinterpret_cast<float4*>(out) + (size_t)row * 4096;

    // ---- load 4 float4 per thread, coalesced, evict-first ----
    float4 v0 = __ldcs(&xrow[tid]);
    float4 v1 = __ldcs(&xrow[tid + 1024]);
    float4 v2 = __ldcs(&xrow[tid + 2048]);
    float4 v3 = __ldcs(&xrow[tid + 3072]);

    // ---- per-thread min/max ----
    float mn = fminf(fminf(fminf(v0.x, v0.y), fminf(v0.z, v0.w)),
                     fminf(fminf(v1.x, v1.y), fminf(v1.z, v1.w)));
    float mx = fmaxf(fmaxf(fmaxf(v0.x, v0.y), fmaxf(v0.z, v0.w)),
                     fmaxf(fmaxf(v1.x, v1.y), fmaxf(v1.z, v1.w)));
    mn = fminf(mn, fminf(fminf(fminf(v2.x, v2.y), fminf(v2.z, v2.w)),
                         fminf(fminf(v3.x, v3.y), fminf(v3.z, v3.w))));
    mx = fmaxf(mx, fmaxf(fmaxf(fmaxf(v2.x, v2.y), fmaxf(v2.z, v2.w)),
                         fmaxf(fmaxf(v3.x, v3.y), fmaxf(v3.z, v3.w))));

    // ---- warp reduce via single REDUX.SYNC on monotonic keys ----
    unsigned kmn = __reduce_min_sync(0xffffffffu, f2key(mn));
    unsigned kmx = __reduce_max_sync(0xffffffffu, f2key(mx));

    // ---- block reduce: partials to smem, ONE barrier, then every warp
    //      redundantly REDUX-reduces the 32 partial keys. ----
    __shared__ unsigned smn[32];
    __shared__ unsigned smx[32];

    const int lane = tid & 31;
    const int wid  = tid >> 5;
    if (lane == 0) { smn[wid] = kmn; smx[wid] = kmx; }
    __syncthreads();

    kmn = __reduce_min_sync(0xffffffffu, smn[lane]);
    kmx = __reduce_max_sync(0xffffffffu, smx[lane]);
    mn = key2f(kmn);
    mx = key2f(kmx);

    const float x_min = fminf(mn, 0.0f);
    const float x_max = fmaxf(mx, 0.0f);
    const float scale = fmaxf((x_max - x_min) * (1.0f / LEVELS), EPS);
    const float zero  = rintf(-x_min / scale);
    const float inv_scale = 1.0f / scale;
    const float qlo = -zero;           // clamp bounds in centered q-domain
    const float qhi = LEVELS - zero;

    // ---- quantize from registers, store evict-first ----
    #define QUANT(e) do { \
        float q = rintf((e) * inv_scale); \
        q = fminf(fmaxf(q, qlo), qhi); \
        (e) = q * scale; \
    } while (0)

    QUANT(v0.x); QUANT(v0.y); QUANT(v0.z); QUANT(v0.w);
    __stcs(&orow[tid],        v0);
    QUANT(v1.x); QUANT(v1.y); QUANT(v1.z); QUANT(v1.w);
    __stcs(&orow[tid + 1024], v1);
    QUANT(v2.x); QUANT(v2.y); QUANT(v2.z); QUANT(v2.w);
    __stcs(&orow[tid + 2048], v2);
    QUANT(v3.x); QUANT(v3.y); QUANT(v3.z); QUANT(v3.w);
    __stcs(&orow[tid + 3072], v3);
    #undef QUANT
}

extern "C" void kernel_launch(void* const* d_in, const int* in_sizes, int n_in,
                              void* d_out, int out_size)
{
    const float* x = (const float*)d_in[0];
    float* out = (float*)d_out;
    perchannel_quant_kernel<<<4096, 1024>>>(x, out);
}